// round 2
// baseline (speedup 1.0000x reference)
#include <cuda_runtime.h>
#include <math.h>

// Problem constants
#define B_      4096
#define SQ_     81
#define D_      256
#define P_      3849
#define NDROP_  7
#define MROWS   (B_ * SQ_)          // 331776
#define SCALE_  0.0625f             // 1/sqrt(256)

// ---------------- device scratch (static, no allocs) ----------------
__device__ float g_pe[84934656];    // MROWS * 256
__device__ float g_G [84934656];    // MROWS * 256
__device__ float g_A [D_ * D_];     // s * Wq @ Wk^T
__device__ float g_Dq2[NDROP_ * D_];// s * Dq @ Wk^T
__device__ float g_wkp[D_];         // Wk @ Wp
__device__ float g_u[D_];           // s * Wq @ bk
__device__ float g_v[D_];           // s * Wk @ bq
__device__ float g_koff[MROWS];
__device__ float g_pu[MROWS];
__device__ float g_pv[MROWS];
__device__ float g_dn[NDROP_];      // s * Dq @ bk
__device__ float g_consts[2];       // [0] = s*(bq.bk), [1] = bk.Wp + bp
__device__ int   g_src2[P_];        // packed col | row<<7 | promo<<14

// ---------------- prep: small weight products ----------------
__global__ __launch_bounds__(256)
void prep_weights(const float* __restrict__ Wq, const float* __restrict__ Wk,
                  const float* __restrict__ Wp, const float* __restrict__ bq,
                  const float* __restrict__ bk, const float* __restrict__ bp,
                  const float* __restrict__ Dq)
{
    int blk = blockIdx.x;
    int t = threadIdx.x;
    if (blk < 256) {
        // A[d][e] = s * sum_i Wq[d,i] * Wk[e,i]   (d = blk, e = t)
        __shared__ float wq[256];
        wq[t] = Wq[blk * 256 + t];
        __syncthreads();
        const float* wkrow = Wk + (size_t)t * 256;
        float acc = 0.f;
        #pragma unroll 8
        for (int i = 0; i < 256; i++) acc = fmaf(wq[i], wkrow[i], acc);
        g_A[blk * 256 + t] = SCALE_ * acc;
    } else if (blk == 256) {
        // Dq2[n][e] = s * sum_i Dq[n,i] * Wk[e,i]
        __shared__ float dq[NDROP_ * 256];
        for (int idx = t; idx < NDROP_ * 256; idx += 256) dq[idx] = Dq[idx];
        __syncthreads();
        const float* wkrow = Wk + (size_t)t * 256;
        float a[NDROP_];
        #pragma unroll
        for (int n = 0; n < NDROP_; n++) a[n] = 0.f;
        for (int i = 0; i < 256; i++) {
            float w = wkrow[i];
            #pragma unroll
            for (int n = 0; n < NDROP_; n++) a[n] = fmaf(dq[n * 256 + i], w, a[n]);
        }
        #pragma unroll
        for (int n = 0; n < NDROP_; n++) g_Dq2[n * 256 + t] = SCALE_ * a[n];
    } else {
        // misc vectors / scalars
        __shared__ float wp[256], bks[256], bqs[256];
        wp[t] = Wp[t]; bks[t] = bk[t]; bqs[t] = bq[t];
        __syncthreads();
        const float* wkrow = Wk + (size_t)t * 256;
        const float* wqrow = Wq + (size_t)t * 256;
        float a0 = 0.f, a1 = 0.f, a2 = 0.f;
        for (int i = 0; i < 256; i++) {
            a0 = fmaf(wkrow[i], wp[i],  a0);
            a1 = fmaf(wqrow[i], bks[i], a1);
            a2 = fmaf(wkrow[i], bqs[i], a2);
        }
        g_wkp[t] = a0;
        g_u[t]   = SCALE_ * a1;
        g_v[t]   = SCALE_ * a2;
        if (t < NDROP_) {
            float s = 0.f;
            for (int i = 0; i < 256; i++) s = fmaf(Dq[t * 256 + i], bks[i], s);
            g_dn[t] = SCALE_ * s;
        }
        if (t == 0) {
            float c = 0.f, kb = 0.f;
            for (int i = 0; i < 256; i++) { c = fmaf(bqs[i], bks[i], c); kb = fmaf(bks[i], wp[i], kb); }
            g_consts[0] = SCALE_ * c;
            g_consts[1] = kb + bp[0];
        }
    }
}

// ---------------- prep: inverse scatter map ----------------
__global__ void prep_src(const void* __restrict__ vraw, const void* __restrict__ vpol)
{
    // detect int64 vs int32 (jax x64 flag unknown): vraw is sorted distinct,
    // so int32 interpretation has r32[1] >= 1; int64 little-endian high words are 0.
    const int* r32 = (const int*)vraw;
    bool is64 = (r32[1] == 0 && r32[3] == 0 && r32[5] == 0);
    int j = blockIdx.x * blockDim.x + threadIdx.x;
    if (j >= P_) return;
    long long r, pol;
    if (is64) {
        r   = ((const long long*)vraw)[j];
        pol = ((const long long*)vpol)[j];
    } else {
        r   = ((const int*)vraw)[j];
        pol = ((const int*)vpol)[j];
    }
    int ri = (int)r;
    int row, col, promo = 0;
    if (ri < 6561)       { row = ri / 81;               col = ri % 81; }
    else if (ri < 13122) { int u2 = ri - 6561;  row = u2 / 81;      col = u2 % 81; promo = 1; }
    else                 { int u2 = ri - 13122; row = 81 + u2 / 81; col = u2 % 81; }
    g_src2[(int)pol] = col | (row << 7) | (promo << 14);
}

// ---------------- big GEMMs (M=331776, N=K=256) ----------------
__device__ __forceinline__ float mishf(float v)
{
    float sp = fmaxf(v, 0.f) + log1pf(__expf(-fabsf(v)));
    return v * tanhf(sp);
}

template<bool FIRST>
__global__ __launch_bounds__(256, 2)
void sgemm256(const float* __restrict__ xin, const float* __restrict__ Win,
              const float* __restrict__ be)
{
    const float* __restrict__ X = FIRST ? xin : g_pe;
    const float* __restrict__ W = FIRST ? Win : g_A;
    float* __restrict__ C       = FIRST ? g_pe : g_G;

    __shared__ float As[16][128];
    __shared__ float Bs[16][128];

    const int tid = threadIdx.x;
    const int tx = tid & 15;
    const int ty = tid >> 4;
    const int m0 = blockIdx.x * 128;
    const int n0 = blockIdx.y * 128;

    const int ar = tid >> 2;           // 0..63
    const int ac = (tid & 3) << 2;     // 0,4,8,12
    const int br = tid >> 5;           // 0..7
    const int bc = (tid & 31) << 2;    // 0..124

    float acc[8][8];
    #pragma unroll
    for (int i = 0; i < 8; i++)
        #pragma unroll
        for (int j = 0; j < 8; j++) acc[i][j] = 0.f;

    for (int k0 = 0; k0 < 256; k0 += 16) {
        #pragma unroll
        for (int h = 0; h < 2; h++) {
            int row = ar + h * 64;
            float4 va = *(const float4*)(X + (size_t)(m0 + row) * 256 + k0 + ac);
            As[ac + 0][row] = va.x; As[ac + 1][row] = va.y;
            As[ac + 2][row] = va.z; As[ac + 3][row] = va.w;
        }
        #pragma unroll
        for (int h = 0; h < 2; h++) {
            int row = br + h * 8;
            *(float4*)&Bs[row][bc] = *(const float4*)(W + (size_t)(k0 + row) * 256 + n0 + bc);
        }
        __syncthreads();
        #pragma unroll
        for (int kk = 0; kk < 16; kk++) {
            float a[8], b[8];
            *(float4*)&a[0] = *(const float4*)&As[kk][ty * 8];
            *(float4*)&a[4] = *(const float4*)&As[kk][ty * 8 + 4];
            *(float4*)&b[0] = *(const float4*)&Bs[kk][tx * 8];
            *(float4*)&b[4] = *(const float4*)&Bs[kk][tx * 8 + 4];
            #pragma unroll
            for (int i = 0; i < 8; i++)
                #pragma unroll
                for (int j = 0; j < 8; j++)
                    acc[i][j] = fmaf(a[i], b[j], acc[i][j]);
        }
        __syncthreads();
    }

    float bv[8];
    #pragma unroll
    for (int j = 0; j < 8; j++) bv[j] = FIRST ? be[n0 + tx * 8 + j] : 0.f;

    #pragma unroll
    for (int i = 0; i < 8; i++) {
        float* crow = C + (size_t)(m0 + ty * 8 + i) * 256 + n0 + tx * 8;
        float outv[8];
        #pragma unroll
        for (int j = 0; j < 8; j++) {
            float v = acc[i][j] + bv[j];
            if (FIRST) v = mishf(v);
            outv[j] = v;
        }
        *(float4*)&crow[0] = *(float4*)&outv[0];
        *(float4*)&crow[4] = *(float4*)&outv[4];
    }
}

// ---------------- per-row dots: koff / pu / pv ----------------
__global__ __launch_bounds__(256)
void koff_kernel()
{
    __shared__ float w0[256], w1[256], w2[256];
    int t = threadIdx.x;
    w0[t] = g_wkp[t]; w1[t] = g_u[t]; w2[t] = g_v[t];
    __syncthreads();
    int warp = t >> 5, lane = t & 31;
    int row = blockIdx.x * 8 + warp;
    const float4* pr = (const float4*)(g_pe + (size_t)row * 256);
    float s0 = 0.f, s1 = 0.f, s2 = 0.f;
    #pragma unroll
    for (int h = 0; h < 2; h++) {
        int i4 = lane + 32 * h;
        float4 p = pr[i4];
        int i = i4 * 4;
        s0 = fmaf(p.x, w0[i], fmaf(p.y, w0[i+1], fmaf(p.z, w0[i+2], fmaf(p.w, w0[i+3], s0))));
        s1 = fmaf(p.x, w1[i], fmaf(p.y, w1[i+1], fmaf(p.z, w1[i+2], fmaf(p.w, w1[i+3], s1))));
        s2 = fmaf(p.x, w2[i], fmaf(p.y, w2[i+1], fmaf(p.z, w2[i+2], fmaf(p.w, w2[i+3], s2))));
    }
    #pragma unroll
    for (int o = 16; o; o >>= 1) {
        s0 += __shfl_down_sync(0xffffffffu, s0, o);
        s1 += __shfl_down_sync(0xffffffffu, s1, o);
        s2 += __shfl_down_sync(0xffffffffu, s2, o);
    }
    if (lane == 0) {
        g_koff[row] = s0 + g_consts[1];
        g_pu[row] = s1;
        g_pv[row] = s2;
    }
}

// ---------------- fused attention + gather ----------------
// smem layout (floats), row stride 89 for transposed tiles (conflict-free)
#define SP_        89
#define OFF_PET    0
#define OFF_MST    22784                 // 256*89
#define OFF_SS     45568                 // +256*89
#define OFF_KOFF   53048                 // +88*85
#define OFF_PU     53136
#define OFF_PV     53224
#define OFF_DN     53312
#define SMEM_FLOATS 53320                // 213,280 bytes

__global__ __launch_bounds__(512)
void attn_gather(float* __restrict__ out)
{
    extern __shared__ float sm[];
    float* peT   = sm + OFF_PET;   // [256][89]  pe_b^T
    float* MsT   = sm + OFF_MST;   // [256][89]  [G_b; Dq2]^T
    float* Ss    = sm + OFF_SS;    // [88][85]
    float* koffS = sm + OFF_KOFF;
    float* puS   = sm + OFF_PU;
    float* pvS   = sm + OFF_PV;
    float* dnS   = sm + OFF_DN;

    const int b = blockIdx.x;
    const int tid = threadIdx.x;

    const float* peB = g_pe + (size_t)b * SQ_ * 256;
    const float* GB  = g_G  + (size_t)b * SQ_ * 256;

    for (int idx = tid; idx < SQ_ * 256; idx += 512) {
        int k = idx >> 8;
        int e = idx & 255;
        peT[e * SP_ + k] = peB[idx];
        MsT[e * SP_ + k] = GB[idx];
    }
    for (int idx = tid; idx < NDROP_ * 256; idx += 512) {
        int n = idx >> 8;
        int e = idx & 255;
        MsT[e * SP_ + 81 + n] = g_Dq2[n * 256 + e];
        peT[e * SP_ + 81 + n] = 0.f;   // zero pad cols 81..87
    }
    if (tid < 88) {
        koffS[tid] = (tid < 81) ? g_koff[(size_t)b * 81 + tid] : 0.f;
        puS[tid]   = (tid < 81) ? g_pu[(size_t)b * 81 + tid] : 0.f;
        pvS[tid]   = (tid < 81) ? g_pv[(size_t)b * 81 + tid] : 0.f;
    }
    if (tid < 8) dnS[tid] = (tid < NDROP_) ? g_dn[tid] : 0.f;
    __syncthreads();

    if (tid < 462) {                     // 22 row-groups x 21 col-groups
        int rg = tid / 21, kg = tid % 21;
        int r0 = rg * 4, k0 = kg * 4;
        float acc[4][4];
        #pragma unroll
        for (int i = 0; i < 4; i++)
            #pragma unroll
            for (int j = 0; j < 4; j++) acc[i][j] = 0.f;

        #pragma unroll 4
        for (int e = 0; e < 256; e++) {
            const float* Mrow = &MsT[e * SP_ + r0];
            const float* Prow = &peT[e * SP_ + k0];
            float a0 = Mrow[0], a1 = Mrow[1], a2 = Mrow[2], a3 = Mrow[3];
            float p0 = Prow[0], p1 = Prow[1], p2 = Prow[2], p3 = Prow[3];
            acc[0][0] = fmaf(a0, p0, acc[0][0]); acc[0][1] = fmaf(a0, p1, acc[0][1]);
            acc[0][2] = fmaf(a0, p2, acc[0][2]); acc[0][3] = fmaf(a0, p3, acc[0][3]);
            acc[1][0] = fmaf(a1, p0, acc[1][0]); acc[1][1] = fmaf(a1, p1, acc[1][1]);
            acc[1][2] = fmaf(a1, p2, acc[1][2]); acc[1][3] = fmaf(a1, p3, acc[1][3]);
            acc[2][0] = fmaf(a2, p0, acc[2][0]); acc[2][1] = fmaf(a2, p1, acc[2][1]);
            acc[2][2] = fmaf(a2, p2, acc[2][2]); acc[2][3] = fmaf(a2, p3, acc[2][3]);
            acc[3][0] = fmaf(a3, p0, acc[3][0]); acc[3][1] = fmaf(a3, p1, acc[3][1]);
            acc[3][2] = fmaf(a3, p2, acc[3][2]); acc[3][3] = fmaf(a3, p3, acc[3][3]);
        }

        float cC = g_consts[0];
        #pragma unroll
        for (int i = 0; i < 4; i++) {
            int r = r0 + i;
            #pragma unroll
            for (int j = 0; j < 4; j++) {
                int k = k0 + j;
                float corr = (r < 81) ? (puS[r] + pvS[k] + cC) : dnS[r - 81];
                Ss[r * 85 + k] = acc[i][j] + corr;
            }
        }
    }
    __syncthreads();

    for (int p = tid; p < P_; p += 512) {
        int code = g_src2[p];
        int col = code & 127;
        int row = (code >> 7) & 127;
        float v = Ss[row * 85 + col];
        if (code & (1 << 14)) v += koffS[col];
        out[(size_t)b * P_ + p] = v;
    }
}

// ---------------- launch ----------------
extern "C" void kernel_launch(void* const* d_in, const int* in_sizes, int n_in,
                              void* d_out, int out_size)
{
    const float* x    = (const float*)d_in[0];
    const float* We   = (const float*)d_in[1];
    const float* be   = (const float*)d_in[2];
    const float* Wq   = (const float*)d_in[3];
    const float* bq   = (const float*)d_in[4];
    const float* Wk   = (const float*)d_in[5];
    const float* bk   = (const float*)d_in[6];
    const float* Wp   = (const float*)d_in[7];
    const float* bp   = (const float*)d_in[8];
    const float* Dq   = (const float*)d_in[9];
    const void*  vraw = d_in[10];
    const void*  vpol = d_in[11];
    float* out = (float*)d_out;

    cudaFuncSetAttribute(attn_gather, cudaFuncAttributeMaxDynamicSharedMemorySize,
                         SMEM_FLOATS * (int)sizeof(float));

    prep_weights<<<258, 256>>>(Wq, Wk, Wp, bq, bk, bp, Dq);
    prep_src<<<(P_ + 255) / 256, 256>>>(vraw, vpol);
    sgemm256<true><<<dim3(MROWS / 128, 2), 256>>>(x, We, be);           // pe = mish(x@We+be)
    sgemm256<false><<<dim3(MROWS / 128, 2), 256>>>(nullptr, nullptr, nullptr); // G = pe@A
    koff_kernel<<<MROWS / 8, 256>>>();
    attn_gather<<<B_, 512, SMEM_FLOATS * (int)sizeof(float)>>>(out);
}